// round 10
// baseline (speedup 1.0000x reference)
#include <cuda_runtime.h>
#include <math.h>

#define BATCH 8
#define SEQ   2048
#define DIM   1024
#define MSZ   (BATCH*SEQ)
typedef unsigned int u32;

// fp32 scratch (allocation-free rule)
__device__ float g_q [(size_t)MSZ*DIM];
__device__ float g_k [(size_t)MSZ*DIM];
__device__ float g_vt[(size_t)BATCH*DIM*SEQ];   // v transposed: [b][e][s]

// ---------------- helpers ----------------
__device__ __forceinline__ void cvt2f(float x, float& h, float& l) {
    u32 uh, ul;
    asm("cvt.rna.tf32.f32 %0, %1;" : "=r"(uh) : "f"(x));
    float r = x - __uint_as_float(uh);
    asm("cvt.rna.tf32.f32 %0, %1;" : "=r"(ul) : "f"(r));
    h = __uint_as_float(uh); l = __uint_as_float(ul);
}
__device__ __forceinline__ void mma8(float* c, const float* a, const float* b) {
    asm volatile(
        "mma.sync.aligned.m16n8k8.row.col.f32.tf32.tf32.f32 "
        "{%0,%1,%2,%3}, {%4,%5,%6,%7}, {%8,%9}, {%0,%1,%2,%3};"
        : "+f"(c[0]), "+f"(c[1]), "+f"(c[2]), "+f"(c[3])
        : "r"(__float_as_uint(a[0])), "r"(__float_as_uint(a[1])),
          "r"(__float_as_uint(a[2])), "r"(__float_as_uint(a[3])),
          "r"(__float_as_uint(b[0])), "r"(__float_as_uint(b[1])));
}

// ---------------------------------------------------------------------------
// C[m,n] = scale * sum_k A[m,k]*B[n,k] (+ bias)   NT gemm, split-TF32.
// CTA tile 128x128, KC=16, 128 threads = 4 warps (2m x 2n), warp tile 64x64.
// Pre-split {Ah,Al,Bh,Bl} smem planes; MMA phase = pure LDS.32 + HMMA with
// MMA:LDS = 1.5 (nprod=3). Double-buffered, 2 CTAs/SM.
// nprod: 3 = hh+lh+hl (QK, projections), 2 = hh+lh (PV; Bl never loaded).
// ---------------------------------------------------------------------------
#define LDK 20                       // smem row stride (floats), KC=16 + pad 4
#define TILE_F (128*LDK)             // 2560 floats per plane tile
#define SMEM_BYTES (2*4*TILE_F*4)    // 2 bufs x {Ah,Al,Bh,Bl} = 81920 B

__global__ __launch_bounds__(128, 2) void gemm_s(
    const float* __restrict__ A, const float* __restrict__ B,
    const float* __restrict__ bias, int biasRow,
    float* __restrict__ C, int K, float scale,
    size_t sA, size_t sB, size_t sC, int ldc, int nprod)
{
    extern __shared__ float sm[];
    const int tid = threadIdx.x;
    const int wid = tid >> 5, lane = tid & 31;
    const int g = lane >> 2, tig = lane & 3;
    const int wm = (wid >> 1) * 64, wn = (wid & 1) * 64;
    const int z = blockIdx.z;

    const float* Ab = A + z * sA + (size_t)(blockIdx.y * 128) * K;
    const float* Bb = B + z * sB + (size_t)(blockIdx.x * 128) * K;

    const int lr  = tid >> 2;        // 0..31 (+32/64/96)
    const int lc4 = (tid & 3) * 4;   // 0,4,8,12

    float acc[4][8][4];
#pragma unroll
    for (int mi = 0; mi < 4; mi++)
#pragma unroll
        for (int ni = 0; ni < 8; ni++)
#pragma unroll
            for (int r = 0; r < 4; r++) acc[mi][ni][r] = 0.0f;

    const int nch = K / 16;
    float4 ra[4], rb[4];

    auto load_regs = [&](int c) {
        const int k0 = c * 16;
#pragma unroll
        for (int i = 0; i < 4; i++) {
            const int row = lr + i * 32;
            ra[i] = *(const float4*)(Ab + (size_t)row * K + k0 + lc4);
            rb[i] = *(const float4*)(Bb + (size_t)row * K + k0 + lc4);
        }
    };
    auto convert_store = [&](int buf) {
        float* Ah = sm + (buf * 4 + 0) * TILE_F;
        float* Al = sm + (buf * 4 + 1) * TILE_F;
        float* Bh = sm + (buf * 4 + 2) * TILE_F;
        float* Bl = sm + (buf * 4 + 3) * TILE_F;
#pragma unroll
        for (int i = 0; i < 4; i++) {
            const int off = (lr + i * 32) * LDK + lc4;
            float4 h, l;
            cvt2f(ra[i].x, h.x, l.x); cvt2f(ra[i].y, h.y, l.y);
            cvt2f(ra[i].z, h.z, l.z); cvt2f(ra[i].w, h.w, l.w);
            *(float4*)(Ah + off) = h; *(float4*)(Al + off) = l;
            cvt2f(rb[i].x, h.x, l.x); cvt2f(rb[i].y, h.y, l.y);
            cvt2f(rb[i].z, h.z, l.z); cvt2f(rb[i].w, h.w, l.w);
            *(float4*)(Bh + off) = h; *(float4*)(Bl + off) = l;
        }
    };

    load_regs(0);
    convert_store(0);
    __syncthreads();
    if (nch > 1) load_regs(1);

    for (int c = 0; c < nch; c++) {
        const int p = c & 1;
        if (c + 1 < nch) convert_store(p ^ 1);   // regs hold chunk c+1
        if (c + 2 < nch) load_regs(c + 2);

        const float* Ash = sm + (p * 4 + 0) * TILE_F;
        const float* Asl = sm + (p * 4 + 1) * TILE_F;
        const float* Bsh = sm + (p * 4 + 2) * TILE_F;
        const float* Bsl = sm + (p * 4 + 3) * TILE_F;

#pragma unroll
        for (int ks = 0; ks < 2; ks++) {
            const int kc = ks * 8 + tig;
            float ah[4][4], al[4][4];
#pragma unroll
            for (int mi = 0; mi < 4; mi++) {
                const int r0 = (wm + mi * 16 + g) * LDK;
                ah[mi][0] = Ash[r0 + kc];
                ah[mi][1] = Ash[r0 + 8 * LDK + kc];
                ah[mi][2] = Ash[r0 + kc + 4];
                ah[mi][3] = Ash[r0 + 8 * LDK + kc + 4];
                al[mi][0] = Asl[r0 + kc];
                al[mi][1] = Asl[r0 + 8 * LDK + kc];
                al[mi][2] = Asl[r0 + kc + 4];
                al[mi][3] = Asl[r0 + 8 * LDK + kc + 4];
            }
#pragma unroll
            for (int half = 0; half < 2; half++) {
                float bh[4][2], bl[4][2];
#pragma unroll
                for (int ni = 0; ni < 4; ni++) {
                    const int rn = (wn + half * 32 + ni * 8 + g) * LDK;
                    bh[ni][0] = Bsh[rn + kc];
                    bh[ni][1] = Bsh[rn + kc + 4];
                    if (nprod == 3) {
                        bl[ni][0] = Bsl[rn + kc];
                        bl[ni][1] = Bsl[rn + kc + 4];
                    }
                }
                // hh
#pragma unroll
                for (int mi = 0; mi < 4; mi++)
#pragma unroll
                    for (int ni = 0; ni < 4; ni++)
                        mma8(acc[mi][half * 4 + ni], ah[mi], bh[ni]);
                // lh
#pragma unroll
                for (int mi = 0; mi < 4; mi++)
#pragma unroll
                    for (int ni = 0; ni < 4; ni++)
                        mma8(acc[mi][half * 4 + ni], al[mi], bh[ni]);
                // hl
                if (nprod == 3) {
#pragma unroll
                    for (int mi = 0; mi < 4; mi++)
#pragma unroll
                        for (int ni = 0; ni < 4; ni++)
                            mma8(acc[mi][half * 4 + ni], ah[mi], bl[ni]);
                }
            }
        }
        __syncthreads();
    }

    // ---------------- epilogue ----------------
    float* Cz = C + z * sC;
#pragma unroll
    for (int mi = 0; mi < 4; mi++) {
        const int row0 = blockIdx.y * 128 + wm + mi * 16 + g;
        const float br0 = (bias && biasRow) ? bias[row0] : 0.0f;
        const float br1 = (bias && biasRow) ? bias[row0 + 8] : 0.0f;
#pragma unroll
        for (int ni = 0; ni < 8; ni++) {
            const int col0 = blockIdx.x * 128 + wn + ni * 8 + tig * 2;
            float2 v0, v1;
            v0.x = acc[mi][ni][0] * scale; v0.y = acc[mi][ni][1] * scale;
            v1.x = acc[mi][ni][2] * scale; v1.y = acc[mi][ni][3] * scale;
            if (bias) {
                if (biasRow) { v0.x += br0; v0.y += br0; v1.x += br1; v1.y += br1; }
                else {
                    const float b0 = bias[col0], b1 = bias[col0 + 1];
                    v0.x += b0; v0.y += b1; v1.x += b0; v1.y += b1;
                }
            }
            *(float2*)(Cz + (size_t)row0 * ldc + col0) = v0;
            *(float2*)(Cz + (size_t)(row0 + 8) * ldc + col0) = v1;
        }
    }
}

// ---------------------------------------------------------------------------
// In-place row softmax over SEQ columns. One block (256 thr) per row.
// ---------------------------------------------------------------------------
__global__ __launch_bounds__(256) void softmax_kernel(float* __restrict__ P)
{
    float* p = P + (size_t)blockIdx.x * SEQ;
    const int tid = threadIdx.x, lane = tid & 31, wid = tid >> 5;
    float4 a = ((const float4*)p)[tid * 2 + 0];
    float4 b = ((const float4*)p)[tid * 2 + 1];
    float x[8] = {a.x, a.y, a.z, a.w, b.x, b.y, b.z, b.w};
    __shared__ float red[8];

    float m = -INFINITY;
#pragma unroll
    for (int i = 0; i < 8; i++) m = fmaxf(m, x[i]);
#pragma unroll
    for (int o = 16; o > 0; o >>= 1) m = fmaxf(m, __shfl_xor_sync(0xffffffffu, m, o));
    if (lane == 0) red[wid] = m;
    __syncthreads();
    float mr = -INFINITY;
#pragma unroll
    for (int i = 0; i < 8; i++) mr = fmaxf(mr, red[i]);
    __syncthreads();

    float s = 0.0f;
#pragma unroll
    for (int i = 0; i < 8; i++) { x[i] = expf(x[i] - mr); s += x[i]; }
#pragma unroll
    for (int o = 16; o > 0; o >>= 1) s += __shfl_xor_sync(0xffffffffu, s, o);
    if (lane == 0) red[wid] = s;
    __syncthreads();
    float tot = 0.0f;
#pragma unroll
    for (int i = 0; i < 8; i++) tot += red[i];
    const float inv = 1.0f / tot;

    float4 o0, o1;
    o0.x = x[0] * inv; o0.y = x[1] * inv; o0.z = x[2] * inv; o0.w = x[3] * inv;
    o1.x = x[4] * inv; o1.y = x[5] * inv; o1.z = x[6] * inv; o1.w = x[7] * inv;
    ((float4*)p)[tid * 2 + 0] = o0;
    ((float4*)p)[tid * 2 + 1] = o1;
}

// ---------------------------------------------------------------------------
extern "C" void kernel_launch(void* const* d_in, const int* in_sizes, int n_in,
                              void* d_out, int out_size)
{
    const float* query = (const float*)d_in[0];
    const float* key   = (const float*)d_in[1];
    const float* value = (const float*)d_in[2];
    const float* Wq = (const float*)d_in[3]; const float* bq = (const float*)d_in[4];
    const float* Wk = (const float*)d_in[5]; const float* bk = (const float*)d_in[6];
    const float* Wv = (const float*)d_in[7]; const float* bv = (const float*)d_in[8];

    float* out_attn = (float*)d_out;
    float* out_smax = (float*)d_out + (size_t)MSZ * DIM;

    float *q, *k, *vt;
    cudaGetSymbolAddress((void**)&q,  g_q);
    cudaGetSymbolAddress((void**)&k,  g_k);
    cudaGetSymbolAddress((void**)&vt, g_vt);

    cudaFuncSetAttribute(gemm_s, cudaFuncAttributeMaxDynamicSharedMemorySize, SMEM_BYTES);

    // 1) q = query @ Wq^T + bq ; k = key @ Wk^T + bk
    {
        dim3 grid(DIM / 128, MSZ / 128, 1);
        gemm_s<<<grid, 128, SMEM_BYTES>>>(query, Wq, bq, 0, q, DIM, 1.0f, 0, 0, 0, DIM, 3);
        gemm_s<<<grid, 128, SMEM_BYTES>>>(key,   Wk, bk, 0, k, DIM, 1.0f, 0, 0, 0, DIM, 3);
    }
    // 2) vT[b,e,s] = Wv[e,:] . value[b,s,:] + bv[e]
    {
        dim3 grid(SEQ / 128, DIM / 128, BATCH);
        gemm_s<<<grid, 128, SMEM_BYTES>>>(Wv, value, bv, 1, vt, DIM, 1.0f,
                                          0, (size_t)SEQ * DIM, (size_t)DIM * SEQ, SEQ, 3);
    }
    // 3) scores = 10 * q @ k^T
    {
        dim3 grid(SEQ / 128, SEQ / 128, BATCH);
        gemm_s<<<grid, 128, SMEM_BYTES>>>(q, k, nullptr, 0, out_smax, DIM, 10.0f,
                                          (size_t)SEQ * DIM, (size_t)SEQ * DIM,
                                          (size_t)SEQ * SEQ, SEQ, 3);
    }
    // 4) softmax in place
    softmax_kernel<<<MSZ, 256>>>(out_smax);
    // 5) out = P @ vT^T  (2 products: hh + lh; Bl never loaded)
    {
        dim3 grid(DIM / 128, SEQ / 128, BATCH);
        gemm_s<<<grid, 128, SMEM_BYTES>>>(out_smax, vt, nullptr, 0, out_attn, SEQ, 1.0f,
                                          (size_t)SEQ * SEQ, (size_t)DIM * SEQ,
                                          (size_t)SEQ * DIM, DIM, 2);
    }
}

// round 11
// speedup vs baseline: 1.6279x; 1.6279x over previous
#include <cuda_runtime.h>
#include <cuda_fp16.h>
#include <math.h>

#define BATCH 8
#define SEQ   2048
#define DIM   1024
#define MSZ   (BATCH*SEQ)
typedef unsigned int u32;

// fp32 scratch (allocation-free rule)
__device__ float g_q [(size_t)MSZ*DIM];
__device__ float g_k [(size_t)MSZ*DIM];
__device__ float g_vt[(size_t)BATCH*DIM*SEQ];   // v transposed: [b][e][s]

#define OPSCALE 64.0f
#define INVSC   (1.0f/4096.0f)

// ---------------- helpers ----------------
__device__ __forceinline__ u32 smem_u32(const void* p) {
    u32 a;
    asm("{ .reg .u64 t; cvta.to.shared.u64 t, %1; cvt.u32.u64 %0, t; }" : "=r"(a) : "l"(p));
    return a;
}
__device__ __forceinline__ void cp16(u32 s, const void* g) {
    asm volatile("cp.async.cg.shared.global [%0], [%1], 16;" :: "r"(s), "l"(g));
}
#define CP_COMMIT() asm volatile("cp.async.commit_group;" ::: "memory")
#define CP_WAIT0()  asm volatile("cp.async.wait_group 0;" ::: "memory")

// fp16 m16n8k16, fp32 accumulate
__device__ __forceinline__ void mma16(float* c, const u32* a, u32 b0, u32 b1) {
    asm volatile(
        "mma.sync.aligned.m16n8k16.row.col.f32.f16.f16.f32 "
        "{%0,%1,%2,%3}, {%4,%5,%6,%7}, {%8,%9}, {%0,%1,%2,%3};"
        : "+f"(c[0]), "+f"(c[1]), "+f"(c[2]), "+f"(c[3])
        : "r"(a[0]), "r"(a[1]), "r"(a[2]), "r"(a[3]), "r"(b0), "r"(b1));
}
// split 2 floats (pre-scaled) into packed h-pair and m-pair
__device__ __forceinline__ void split2(float x0, float x1, u32& hp, u32& mp) {
    __half2 h = __floats2half2_rn(x0, x1);
    float2 hf = __half22float2(h);
    __half2 m = __floats2half2_rn(x0 - hf.x, x1 - hf.y);
    hp = *(u32*)&h; mp = *(u32*)&m;
}

// ---------------------------------------------------------------------------
// C[m,n] = scale * sum_k A[m,k]*B[n,k] (+ bias)   NT gemm, split-FP16.
// CTA 128x128, KC=32, 256 threads = 8 warps (2m x 4n), warp tile 64x32.
// cp.async fills raw fp32 staging (double buffered); convert phase scales by
// 64 and splits into {Ah,Am,Bh,Bm} fp16 planes (single buffer); MMA phase is
// pure LDS.32 + HMMA m16n8k16. 2 CTAs/SM.
// nprod: 3 = hh+mh+hm, 2 = hh+mh (PV: B lo-plane correction dropped).
// ---------------------------------------------------------------------------
#define LDT 36                         // raw stride (floats)
#define RAWP (128*LDT)                 // 4608 floats per raw plane
#define RAWBUF (2*RAWP)                // A+B raw
#define RAW_BYTES (2*RAWBUF*4)         // 73728
#define LDH 20                         // fp16 plane stride in u32 units (40 fp16)
#define PLANE_U32 (128*LDH)            // 2560 u32
#define PLANES_OFF RAW_BYTES
#define SMEM_BYTES (RAW_BYTES + 4*PLANE_U32*4)   // 114688

__global__ __launch_bounds__(256, 2) void gemm_h(
    const float* __restrict__ A, const float* __restrict__ B,
    const float* __restrict__ bias, int biasRow,
    float* __restrict__ C, int K, float scale,
    size_t sA, size_t sB, size_t sC, int ldc, int nprod)
{
    extern __shared__ float sm[];
    const u32 sbase = smem_u32(sm);
    u32* pl = (u32*)((char*)sm + PLANES_OFF);
    const int tid = threadIdx.x;
    const int wid = tid >> 5, lane = tid & 31;
    const int g = lane >> 2, tig = lane & 3;
    const int wm = (wid >> 2) * 64, wn = (wid & 3) * 32;
    const int z = blockIdx.z;

    const float* Ab = A + z * sA + (size_t)(blockIdx.y * 128) * K;
    const float* Bb = B + z * sB + (size_t)(blockIdx.x * 128) * K;

    const int lr  = tid >> 3;        // 0..31 (+32/64/96)
    const int lc4 = (tid & 7) * 4;   // 0..28

    float acc[4][4][4];
#pragma unroll
    for (int mi = 0; mi < 4; mi++)
#pragma unroll
        for (int ni = 0; ni < 4; ni++)
#pragma unroll
            for (int r = 0; r < 4; r++) acc[mi][ni][r] = 0.0f;

    const int nch = K / 32;

    // cp.async chunk c into raw buffer buf
    auto issue = [&](int c, int buf) {
        const int k0 = c * 32;
        const u32 sA0 = sbase + (u32)(buf * RAWBUF) * 4;
        const u32 sB0 = sA0 + (u32)RAWP * 4;
#pragma unroll
        for (int i = 0; i < 4; i++) {
            const int row = lr + i * 32;
            cp16(sA0 + (u32)(row * LDT + lc4) * 4, Ab + (size_t)row * K + k0 + lc4);
            cp16(sB0 + (u32)(row * LDT + lc4) * 4, Bb + (size_t)row * K + k0 + lc4);
        }
        CP_COMMIT();
    };
    // raw[buf] -> fp16 planes (scaled by OPSCALE)
    auto convert = [&](int buf) {
        const float* Ar = sm + buf * RAWBUF;
        const float* Br = Ar + RAWP;
        u32* Ah = pl;
        u32* Am = pl + PLANE_U32;
        u32* Bh = pl + 2 * PLANE_U32;
        u32* Bm = pl + 3 * PLANE_U32;
#pragma unroll
        for (int i = 0; i < 4; i++) {
            const int row = lr + i * 32;
            const int roff = row * LDT + lc4;
            const int poff = row * LDH + (lc4 >> 1);   // u32 units
            float4 a = *(const float4*)(Ar + roff);
            u32 h0, m0, h1, m1;
            split2(a.x * OPSCALE, a.y * OPSCALE, h0, m0);
            split2(a.z * OPSCALE, a.w * OPSCALE, h1, m1);
            *(uint2*)(Ah + poff) = make_uint2(h0, h1);
            *(uint2*)(Am + poff) = make_uint2(m0, m1);
            float4 b = *(const float4*)(Br + roff);
            split2(b.x * OPSCALE, b.y * OPSCALE, h0, m0);
            split2(b.z * OPSCALE, b.w * OPSCALE, h1, m1);
            *(uint2*)(Bh + poff) = make_uint2(h0, h1);
            *(uint2*)(Bm + poff) = make_uint2(m0, m1);
        }
    };

    issue(0, 0);

    for (int c = 0; c < nch; c++) {
        const int p = c & 1;
        CP_WAIT0();
        __syncthreads();                     // raw[p] ready; planes free
        if (c + 1 < nch) issue(c + 1, p ^ 1);
        convert(p);
        __syncthreads();                     // planes ready

        const u32* Ah = pl;
        const u32* Am = pl + PLANE_U32;
        const u32* Bh = pl + 2 * PLANE_U32;
        const u32* Bm = pl + 3 * PLANE_U32;

#pragma unroll
        for (int ks = 0; ks < 2; ks++) {
            const int kc = ks * 8 + tig;     // u32-unit k offset
            u32 ah[4][4], am[4][4];
#pragma unroll
            for (int mi = 0; mi < 4; mi++) {
                const int r0 = (wm + mi * 16 + g) * LDH;
                const int r1 = r0 + 8 * LDH;
                ah[mi][0] = Ah[r0 + kc]; ah[mi][1] = Ah[r1 + kc];
                ah[mi][2] = Ah[r0 + kc + 4]; ah[mi][3] = Ah[r1 + kc + 4];
                am[mi][0] = Am[r0 + kc]; am[mi][1] = Am[r1 + kc];
                am[mi][2] = Am[r0 + kc + 4]; am[mi][3] = Am[r1 + kc + 4];
            }
#pragma unroll
            for (int ni = 0; ni < 4; ni++) {
                const int rn = (wn + ni * 8 + g) * LDH;
                const u32 bh0 = Bh[rn + kc], bh1 = Bh[rn + kc + 4];
                // hh + mh
#pragma unroll
                for (int mi = 0; mi < 4; mi++) mma16(acc[mi][ni], ah[mi], bh0, bh1);
#pragma unroll
                for (int mi = 0; mi < 4; mi++) mma16(acc[mi][ni], am[mi], bh0, bh1);
                if (nprod == 3) {
                    const u32 bm0 = Bm[rn + kc], bm1 = Bm[rn + kc + 4];
#pragma unroll
                    for (int mi = 0; mi < 4; mi++) mma16(acc[mi][ni], ah[mi], bm0, bm1);
                }
            }
        }
        __syncthreads();                     // MMA done before planes reused
    }

    // ---------------- epilogue ----------------
    float* Cz = C + z * sC;
#pragma unroll
    for (int mi = 0; mi < 4; mi++) {
        const int row0 = blockIdx.y * 128 + wm + mi * 16 + g;
        const float br0 = (bias && biasRow) ? bias[row0] : 0.0f;
        const float br1 = (bias && biasRow) ? bias[row0 + 8] : 0.0f;
#pragma unroll
        for (int ni = 0; ni < 4; ni++) {
            const int col0 = blockIdx.x * 128 + wn + ni * 8 + tig * 2;
            float2 v0, v1;
            v0.x = acc[mi][ni][0] * scale; v0.y = acc[mi][ni][1] * scale;
            v1.x = acc[mi][ni][2] * scale; v1.y = acc[mi][ni][3] * scale;
            if (bias) {
                if (biasRow) { v0.x += br0; v0.y += br0; v1.x += br1; v1.y += br1; }
                else {
                    const float b0 = bias[col0], b1 = bias[col0 + 1];
                    v0.x += b0; v0.y += b1; v1.x += b0; v1.y += b1;
                }
            }
            *(float2*)(Cz + (size_t)row0 * ldc + col0) = v0;
            *(float2*)(Cz + (size_t)(row0 + 8) * ldc + col0) = v1;
        }
    }
}

// ---------------------------------------------------------------------------
// In-place row softmax over SEQ columns. One block (256 thr) per row.
// ---------------------------------------------------------------------------
__global__ __launch_bounds__(256) void softmax_kernel(float* __restrict__ P)
{
    float* p = P + (size_t)blockIdx.x * SEQ;
    const int tid = threadIdx.x, lane = tid & 31, wid = tid >> 5;
    float4 a = ((const float4*)p)[tid * 2 + 0];
    float4 b = ((const float4*)p)[tid * 2 + 1];
    float x[8] = {a.x, a.y, a.z, a.w, b.x, b.y, b.z, b.w};
    __shared__ float red[8];

    float m = -INFINITY;
#pragma unroll
    for (int i = 0; i < 8; i++) m = fmaxf(m, x[i]);
#pragma unroll
    for (int o = 16; o > 0; o >>= 1) m = fmaxf(m, __shfl_xor_sync(0xffffffffu, m, o));
    if (lane == 0) red[wid] = m;
    __syncthreads();
    float mr = -INFINITY;
#pragma unroll
    for (int i = 0; i < 8; i++) mr = fmaxf(mr, red[i]);
    __syncthreads();

    float s = 0.0f;
#pragma unroll
    for (int i = 0; i < 8; i++) { x[i] = expf(x[i] - mr); s += x[i]; }
#pragma unroll
    for (int o = 16; o > 0; o >>= 1) s += __shfl_xor_sync(0xffffffffu, s, o);
    if (lane == 0) red[wid] = s;
    __syncthreads();
    float tot = 0.0f;
#pragma unroll
    for (int i = 0; i < 8; i++) tot += red[i];
    const float inv = 1.0f / tot;

    float4 o0, o1;
    o0.x = x[0] * inv; o0.y = x[1] * inv; o0.z = x[2] * inv; o0.w = x[3] * inv;
    o1.x = x[4] * inv; o1.y = x[5] * inv; o1.z = x[6] * inv; o1.w = x[7] * inv;
    ((float4*)p)[tid * 2 + 0] = o0;
    ((float4*)p)[tid * 2 + 1] = o1;
}

// ---------------------------------------------------------------------------
extern "C" void kernel_launch(void* const* d_in, const int* in_sizes, int n_in,
                              void* d_out, int out_size)
{
    const float* query = (const float*)d_in[0];
    const float* key   = (const float*)d_in[1];
    const float* value = (const float*)d_in[2];
    const float* Wq = (const float*)d_in[3]; const float* bq = (const float*)d_in[4];
    const float* Wk = (const float*)d_in[5]; const float* bk = (const float*)d_in[6];
    const float* Wv = (const float*)d_in[7]; const float* bv = (const float*)d_in[8];

    float* out_attn = (float*)d_out;
    float* out_smax = (float*)d_out + (size_t)MSZ * DIM;

    float *q, *k, *vt;
    cudaGetSymbolAddress((void**)&q,  g_q);
    cudaGetSymbolAddress((void**)&k,  g_k);
    cudaGetSymbolAddress((void**)&vt, g_vt);

    cudaFuncSetAttribute(gemm_h, cudaFuncAttributeMaxDynamicSharedMemorySize, SMEM_BYTES);

    // 1) q = query @ Wq^T + bq ; k = key @ Wk^T + bk
    {
        dim3 grid(DIM / 128, MSZ / 128, 1);
        gemm_h<<<grid, 256, SMEM_BYTES>>>(query, Wq, bq, 0, q, DIM, INVSC, 0, 0, 0, DIM, 3);
        gemm_h<<<grid, 256, SMEM_BYTES>>>(key,   Wk, bk, 0, k, DIM, INVSC, 0, 0, 0, DIM, 3);
    }
    // 2) vT[b,e,s] = Wv[e,:] . value[b,s,:] + bv[e]
    {
        dim3 grid(SEQ / 128, DIM / 128, BATCH);
        gemm_h<<<grid, 256, SMEM_BYTES>>>(Wv, value, bv, 1, vt, DIM, INVSC,
                                          0, (size_t)SEQ * DIM, (size_t)DIM * SEQ, SEQ, 3);
    }
    // 3) scores = 10 * q @ k^T
    {
        dim3 grid(SEQ / 128, SEQ / 128, BATCH);
        gemm_h<<<grid, 256, SMEM_BYTES>>>(q, k, nullptr, 0, out_smax, DIM, 10.0f * INVSC,
                                          (size_t)SEQ * DIM, (size_t)SEQ * DIM,
                                          (size_t)SEQ * SEQ, SEQ, 3);
    }
    // 4) softmax in place
    softmax_kernel<<<MSZ, 256>>>(out_smax);
    // 5) out = P @ vT^T  (2 products: hh + mh)
    {
        dim3 grid(DIM / 128, SEQ / 128, BATCH);
        gemm_h<<<grid, 256, SMEM_BYTES>>>(out_smax, vt, nullptr, 0, out_attn, SEQ, INVSC,
                                          (size_t)SEQ * SEQ, (size_t)DIM * SEQ,
                                          (size_t)SEQ * DIM, DIM, 2);
    }
}

// round 12
// speedup vs baseline: 1.7190x; 1.0560x over previous
#include <cuda_runtime.h>
#include <cuda_fp16.h>
#include <math.h>

#define BATCH 8
#define SEQ   2048
#define DIM   1024
#define MSZ   (BATCH*SEQ)
typedef unsigned int u32;

// fp32 scratch (allocation-free rule)
__device__ float g_q [(size_t)MSZ*DIM];
__device__ float g_k [(size_t)MSZ*DIM];
__device__ float g_vt[(size_t)BATCH*DIM*SEQ];   // v transposed: [b][e][s]

#define OPSCALE 64.0f
#define INVSC   (1.0f/4096.0f)

// ---------------- helpers ----------------
// fp16 m16n8k16, fp32 accumulate
__device__ __forceinline__ void mma16(float* c, const u32* a, u32 b0, u32 b1) {
    asm volatile(
        "mma.sync.aligned.m16n8k16.row.col.f32.f16.f16.f32 "
        "{%0,%1,%2,%3}, {%4,%5,%6,%7}, {%8,%9}, {%0,%1,%2,%3};"
        : "+f"(c[0]), "+f"(c[1]), "+f"(c[2]), "+f"(c[3])
        : "r"(a[0]), "r"(a[1]), "r"(a[2]), "r"(a[3]), "r"(b0), "r"(b1));
}
// split 2 floats (pre-scaled) into packed h-pair and m-pair
__device__ __forceinline__ void split2(float x0, float x1, u32& hp, u32& mp) {
    __half2 h = __floats2half2_rn(x0, x1);
    float2 hf = __half22float2(h);
    __half2 m = __floats2half2_rn(x0 - hf.x, x1 - hf.y);
    hp = *(u32*)&h; mp = *(u32*)&m;
}
__device__ __forceinline__ void split4h(const float4& v, u32& h0, u32& h1) {
    __half2 a = __floats2half2_rn(v.x * OPSCALE, v.y * OPSCALE);
    __half2 b = __floats2half2_rn(v.z * OPSCALE, v.w * OPSCALE);
    h0 = *(u32*)&a; h1 = *(u32*)&b;
}

// ---------------------------------------------------------------------------
// C[m,n] = scale * sum_k A[m,k]*B[n,k] (+ bias)   NT gemm, split-FP16.
// CTA 128x128, KC=32, 256 threads = 8 warps (2m x 4n), warp tile 64x32.
// LDG->regs (2-chunk prefetch), convert (xOPSCALE) -> {Ah,Am,Bh,Bm} fp16
// planes (double buffered), MMA phase = pure LDS.32 + HMMA m16n8k16.
// nprod: 3 = hh+mh+hm, 2 = hh+mh (PV: Bm never computed/stored/loaded).
// ---------------------------------------------------------------------------
#define LDH 20                         // plane row stride in u32 (40 fp16)
#define PLANE_U32 (128*LDH)            // 2560 u32 per plane
#define SMEM_BYTES (2*4*PLANE_U32*4)   // 2 bufs x {Ah,Am,Bh,Bm} = 81920 B

__global__ __launch_bounds__(256, 1) void gemm_h(
    const float* __restrict__ A, const float* __restrict__ B,
    const float* __restrict__ bias, int biasRow,
    float* __restrict__ C, int K, float scale,
    size_t sA, size_t sB, size_t sC, int ldc, int nprod)
{
    extern __shared__ u32 pl[];
    const int tid = threadIdx.x;
    const int wid = tid >> 5, lane = tid & 31;
    const int g = lane >> 2, tig = lane & 3;
    const int wm = (wid >> 2) * 64, wn = (wid & 3) * 32;
    const int z = blockIdx.z;

    const float* Ab = A + z * sA + (size_t)(blockIdx.y * 128) * K;
    const float* Bb = B + z * sB + (size_t)(blockIdx.x * 128) * K;

    const int lr  = tid >> 3;        // 0..31 (+32/64/96)
    const int lc4 = (tid & 7) * 4;   // 0..28

    float acc[4][4][4];
#pragma unroll
    for (int mi = 0; mi < 4; mi++)
#pragma unroll
        for (int ni = 0; ni < 4; ni++)
#pragma unroll
            for (int r = 0; r < 4; r++) acc[mi][ni][r] = 0.0f;

    const int nch = K / 32;
    float4 ra[4], rb[4];

    auto load_regs = [&](int c) {
        const int k0 = c * 32;
#pragma unroll
        for (int i = 0; i < 4; i++) {
            const int row = lr + i * 32;
            ra[i] = *(const float4*)(Ab + (size_t)row * K + k0 + lc4);
            rb[i] = *(const float4*)(Bb + (size_t)row * K + k0 + lc4);
        }
    };
    auto convert_store = [&](int buf) {
        u32* Ah = pl + (buf * 4 + 0) * PLANE_U32;
        u32* Am = pl + (buf * 4 + 1) * PLANE_U32;
        u32* Bh = pl + (buf * 4 + 2) * PLANE_U32;
        u32* Bm = pl + (buf * 4 + 3) * PLANE_U32;
#pragma unroll
        for (int i = 0; i < 4; i++) {
            const int poff = (lr + i * 32) * LDH + (lc4 >> 1);
            u32 h0, m0, h1, m1;
            split2(ra[i].x * OPSCALE, ra[i].y * OPSCALE, h0, m0);
            split2(ra[i].z * OPSCALE, ra[i].w * OPSCALE, h1, m1);
            *(uint2*)(Ah + poff) = make_uint2(h0, h1);
            *(uint2*)(Am + poff) = make_uint2(m0, m1);
            if (nprod == 3) {
                split2(rb[i].x * OPSCALE, rb[i].y * OPSCALE, h0, m0);
                split2(rb[i].z * OPSCALE, rb[i].w * OPSCALE, h1, m1);
                *(uint2*)(Bh + poff) = make_uint2(h0, h1);
                *(uint2*)(Bm + poff) = make_uint2(m0, m1);
            } else {
                split4h(rb[i], h0, h1);
                *(uint2*)(Bh + poff) = make_uint2(h0, h1);
            }
        }
    };

    load_regs(0);
    convert_store(0);
    __syncthreads();
    if (nch > 1) load_regs(1);

    for (int c = 0; c < nch; c++) {
        const int p = c & 1;
        if (c + 1 < nch) convert_store(p ^ 1);   // regs hold chunk c+1
        if (c + 2 < nch) load_regs(c + 2);

        const u32* Ah = pl + (p * 4 + 0) * PLANE_U32;
        const u32* Am = pl + (p * 4 + 1) * PLANE_U32;
        const u32* Bh = pl + (p * 4 + 2) * PLANE_U32;
        const u32* Bm = pl + (p * 4 + 3) * PLANE_U32;

#pragma unroll
        for (int ks = 0; ks < 2; ks++) {
            const int kc = ks * 8 + tig;     // u32-unit k offset
            u32 ah[4][4], am[4][4];
#pragma unroll
            for (int mi = 0; mi < 4; mi++) {
                const int r0 = (wm + mi * 16 + g) * LDH;
                const int r1 = r0 + 8 * LDH;
                ah[mi][0] = Ah[r0 + kc]; ah[mi][1] = Ah[r1 + kc];
                ah[mi][2] = Ah[r0 + kc + 4]; ah[mi][3] = Ah[r1 + kc + 4];
                am[mi][0] = Am[r0 + kc]; am[mi][1] = Am[r1 + kc];
                am[mi][2] = Am[r0 + kc + 4]; am[mi][3] = Am[r1 + kc + 4];
            }
#pragma unroll
            for (int ni = 0; ni < 4; ni++) {
                const int rn = (wn + ni * 8 + g) * LDH;
                const u32 bh0 = Bh[rn + kc], bh1 = Bh[rn + kc + 4];
#pragma unroll
                for (int mi = 0; mi < 4; mi++) mma16(acc[mi][ni], ah[mi], bh0, bh1);
#pragma unroll
                for (int mi = 0; mi < 4; mi++) mma16(acc[mi][ni], am[mi], bh0, bh1);
                if (nprod == 3) {
                    const u32 bm0 = Bm[rn + kc], bm1 = Bm[rn + kc + 4];
#pragma unroll
                    for (int mi = 0; mi < 4; mi++) mma16(acc[mi][ni], ah[mi], bm0, bm1);
                }
            }
        }
        __syncthreads();
    }

    // ---------------- epilogue ----------------
    float* Cz = C + z * sC;
#pragma unroll
    for (int mi = 0; mi < 4; mi++) {
        const int row0 = blockIdx.y * 128 + wm + mi * 16 + g;
        const float br0 = (bias && biasRow) ? bias[row0] : 0.0f;
        const float br1 = (bias && biasRow) ? bias[row0 + 8] : 0.0f;
#pragma unroll
        for (int ni = 0; ni < 4; ni++) {
            const int col0 = blockIdx.x * 128 + wn + ni * 8 + tig * 2;
            float2 v0, v1;
            v0.x = acc[mi][ni][0] * scale; v0.y = acc[mi][ni][1] * scale;
            v1.x = acc[mi][ni][2] * scale; v1.y = acc[mi][ni][3] * scale;
            if (bias) {
                if (biasRow) { v0.x += br0; v0.y += br0; v1.x += br1; v1.y += br1; }
                else {
                    const float b0 = bias[col0], b1 = bias[col0 + 1];
                    v0.x += b0; v0.y += b1; v1.x += b0; v1.y += b1;
                }
            }
            *(float2*)(Cz + (size_t)row0 * ldc + col0) = v0;
            *(float2*)(Cz + (size_t)(row0 + 8) * ldc + col0) = v1;
        }
    }
}

// ---------------------------------------------------------------------------
// In-place row softmax over SEQ columns. One block (256 thr) per row.
// ---------------------------------------------------------------------------
__global__ __launch_bounds__(256) void softmax_kernel(float* __restrict__ P)
{
    float* p = P + (size_t)blockIdx.x * SEQ;
    const int tid = threadIdx.x, lane = tid & 31, wid = tid >> 5;
    float4 a = ((const float4*)p)[tid * 2 + 0];
    float4 b = ((const float4*)p)[tid * 2 + 1];
    float x[8] = {a.x, a.y, a.z, a.w, b.x, b.y, b.z, b.w};
    __shared__ float red[8];

    float m = -INFINITY;
#pragma unroll
    for (int i = 0; i < 8; i++) m = fmaxf(m, x[i]);
#pragma unroll
    for (int o = 16; o > 0; o >>= 1) m = fmaxf(m, __shfl_xor_sync(0xffffffffu, m, o));
    if (lane == 0) red[wid] = m;
    __syncthreads();
    float mr = -INFINITY;
#pragma unroll
    for (int i = 0; i < 8; i++) mr = fmaxf(mr, red[i]);
    __syncthreads();

    float s = 0.0f;
#pragma unroll
    for (int i = 0; i < 8; i++) { x[i] = expf(x[i] - mr); s += x[i]; }
#pragma unroll
    for (int o = 16; o > 0; o >>= 1) s += __shfl_xor_sync(0xffffffffu, s, o);
    if (lane == 0) red[wid] = s;
    __syncthreads();
    float tot = 0.0f;
#pragma unroll
    for (int i = 0; i < 8; i++) tot += red[i];
    const float inv = 1.0f / tot;

    float4 o0, o1;
    o0.x = x[0] * inv; o0.y = x[1] * inv; o0.z = x[2] * inv; o0.w = x[3] * inv;
    o1.x = x[4] * inv; o1.y = x[5] * inv; o1.z = x[6] * inv; o1.w = x[7] * inv;
    ((float4*)p)[tid * 2 + 0] = o0;
    ((float4*)p)[tid * 2 + 1] = o1;
}

// ---------------------------------------------------------------------------
extern "C" void kernel_launch(void* const* d_in, const int* in_sizes, int n_in,
                              void* d_out, int out_size)
{
    const float* query = (const float*)d_in[0];
    const float* key   = (const float*)d_in[1];
    const float* value = (const float*)d_in[2];
    const float* Wq = (const float*)d_in[3]; const float* bq = (const float*)d_in[4];
    const float* Wk = (const float*)d_in[5]; const float* bk = (const float*)d_in[6];
    const float* Wv = (const float*)d_in[7]; const float* bv = (const float*)d_in[8];

    float* out_attn = (float*)d_out;
    float* out_smax = (float*)d_out + (size_t)MSZ * DIM;

    float *q, *k, *vt;
    cudaGetSymbolAddress((void**)&q,  g_q);
    cudaGetSymbolAddress((void**)&k,  g_k);
    cudaGetSymbolAddress((void**)&vt, g_vt);

    cudaFuncSetAttribute(gemm_h, cudaFuncAttributeMaxDynamicSharedMemorySize, SMEM_BYTES);

    // 1) q = query @ Wq^T + bq ; k = key @ Wk^T + bk
    {
        dim3 grid(DIM / 128, MSZ / 128, 1);
        gemm_h<<<grid, 256, SMEM_BYTES>>>(query, Wq, bq, 0, q, DIM, INVSC, 0, 0, 0, DIM, 3);
        gemm_h<<<grid, 256, SMEM_BYTES>>>(key,   Wk, bk, 0, k, DIM, INVSC, 0, 0, 0, DIM, 3);
    }
    // 2) vT[b,e,s] = Wv[e,:] . value[b,s,:] + bv[e]
    {
        dim3 grid(SEQ / 128, DIM / 128, BATCH);
        gemm_h<<<grid, 256, SMEM_BYTES>>>(Wv, value, bv, 1, vt, DIM, INVSC,
                                          0, (size_t)SEQ * DIM, (size_t)DIM * SEQ, SEQ, 3);
    }
    // 3) scores = 10 * q @ k^T
    {
        dim3 grid(SEQ / 128, SEQ / 128, BATCH);
        gemm_h<<<grid, 256, SMEM_BYTES>>>(q, k, nullptr, 0, out_smax, DIM, 10.0f * INVSC,
                                          (size_t)SEQ * DIM, (size_t)SEQ * DIM,
                                          (size_t)SEQ * SEQ, SEQ, 3);
    }
    // 4) softmax in place
    softmax_kernel<<<MSZ, 256>>>(out_smax);
    // 5) out = P @ vT^T  (2 products: hh + mh)
    {
        dim3 grid(DIM / 128, SEQ / 128, BATCH);
        gemm_h<<<grid, 256, SMEM_BYTES>>>(out_smax, vt, nullptr, 0, out_attn, SEQ, INVSC,
                                          (size_t)SEQ * SEQ, (size_t)DIM * SEQ,
                                          (size_t)SEQ * DIM, DIM, 2);
    }
}

// round 13
// speedup vs baseline: 1.7307x; 1.0068x over previous
#include <cuda_runtime.h>
#include <cuda_fp16.h>
#include <math.h>

#define BATCH 8
#define SEQ   2048
#define DIM   1024
#define MSZ   (BATCH*SEQ)
typedef unsigned int u32;

#define NXD ((size_t)MSZ*DIM)
#define NPP ((size_t)BATCH*SEQ*SEQ)

// fp16 {hi,mid} planes, pre-scaled by OPSCALE (allocation-free rule)
__device__ __half g_qh[NXD], g_qm[NXD];
__device__ __half g_kh[NXD], g_km[NXD];
__device__ __half g_vth[NXD], g_vtm[NXD];   // v^T: [b][e][s]
__device__ __half g_ph[NPP], g_pm[NPP];

#define OPSCALE 64.0f
#define INVSC   (1.0f/4096.0f)

// ---------------- helpers ----------------
__device__ __forceinline__ u32 smem_u32(const void* p) {
    u32 a;
    asm("{ .reg .u64 t; cvta.to.shared.u64 t, %1; cvt.u32.u64 %0, t; }" : "=r"(a) : "l"(p));
    return a;
}
__device__ __forceinline__ void cp16(u32 s, const void* g) {
    asm volatile("cp.async.cg.shared.global [%0], [%1], 16;" :: "r"(s), "l"(g));
}
#define CP_COMMIT() asm volatile("cp.async.commit_group;" ::: "memory")
#define CP_WAIT0()  asm volatile("cp.async.wait_group 0;" ::: "memory")

__device__ __forceinline__ void mma16(float* c, const u32* a, u32 b0, u32 b1) {
    asm volatile(
        "mma.sync.aligned.m16n8k16.row.col.f32.f16.f16.f32 "
        "{%0,%1,%2,%3}, {%4,%5,%6,%7}, {%8,%9}, {%0,%1,%2,%3};"
        : "+f"(c[0]), "+f"(c[1]), "+f"(c[2]), "+f"(c[3])
        : "r"(a[0]), "r"(a[1]), "r"(a[2]), "r"(a[3]), "r"(b0), "r"(b1));
}
__device__ __forceinline__ void split2(float x0, float x1, u32& hp, u32& mp) {
    __half2 h = __floats2half2_rn(x0, x1);
    float2 hf = __half22float2(h);
    __half2 m = __floats2half2_rn(x0 - hf.x, x1 - hf.y);
    hp = *(u32*)&h; mp = *(u32*)&m;
}

// ---------------------------------------------------------------------------
// gemm_proj: raw fp32 NT gemm -> fp16 {h,m} plane outputs (scaled by OPSCALE).
// R12-proven core: CTA 128x128, KC=32, 256 thr (8 warps 2m x 4n), warp 64x32.
// ---------------------------------------------------------------------------
#define LDH 20                         // plane row stride in u32 (40 fp16)
#define PLANE_U32 (128*LDH)            // 2560 u32 per plane (10240 B)
#define SMEM_BYTES (2*4*PLANE_U32*4)   // 2 bufs x {Ah,Am,Bh,Bm} = 81920 B

__global__ __launch_bounds__(256, 1) void gemm_proj(
    const float* __restrict__ A, const float* __restrict__ B,
    const float* __restrict__ bias, int biasRow,
    __half* __restrict__ Ch, __half* __restrict__ Cm, int K,
    size_t sA, size_t sB, size_t sC, int ldc)
{
    extern __shared__ u32 pl[];
    const int tid = threadIdx.x;
    const int wid = tid >> 5, lane = tid & 31;
    const int g = lane >> 2, tig = lane & 3;
    const int wm = (wid >> 2) * 64, wn = (wid & 3) * 32;
    const int z = blockIdx.z;

    const float* Ab = A + z * sA + (size_t)(blockIdx.y * 128) * K;
    const float* Bb = B + z * sB + (size_t)(blockIdx.x * 128) * K;

    const int lr  = tid >> 3;
    const int lc4 = (tid & 7) * 4;

    float acc[4][4][4];
#pragma unroll
    for (int mi = 0; mi < 4; mi++)
#pragma unroll
        for (int ni = 0; ni < 4; ni++)
#pragma unroll
            for (int r = 0; r < 4; r++) acc[mi][ni][r] = 0.0f;

    const int nch = K / 32;
    float4 ra[4], rb[4];

    auto load_regs = [&](int c) {
        const int k0 = c * 32;
#pragma unroll
        for (int i = 0; i < 4; i++) {
            const int row = lr + i * 32;
            ra[i] = *(const float4*)(Ab + (size_t)row * K + k0 + lc4);
            rb[i] = *(const float4*)(Bb + (size_t)row * K + k0 + lc4);
        }
    };
    auto convert_store = [&](int buf) {
        u32* Ah = pl + (buf * 4 + 0) * PLANE_U32;
        u32* Am = pl + (buf * 4 + 1) * PLANE_U32;
        u32* Bh = pl + (buf * 4 + 2) * PLANE_U32;
        u32* Bm = pl + (buf * 4 + 3) * PLANE_U32;
#pragma unroll
        for (int i = 0; i < 4; i++) {
            const int poff = (lr + i * 32) * LDH + (lc4 >> 1);
            u32 h0, m0, h1, m1;
            split2(ra[i].x * OPSCALE, ra[i].y * OPSCALE, h0, m0);
            split2(ra[i].z * OPSCALE, ra[i].w * OPSCALE, h1, m1);
            *(uint2*)(Ah + poff) = make_uint2(h0, h1);
            *(uint2*)(Am + poff) = make_uint2(m0, m1);
            split2(rb[i].x * OPSCALE, rb[i].y * OPSCALE, h0, m0);
            split2(rb[i].z * OPSCALE, rb[i].w * OPSCALE, h1, m1);
            *(uint2*)(Bh + poff) = make_uint2(h0, h1);
            *(uint2*)(Bm + poff) = make_uint2(m0, m1);
        }
    };

    load_regs(0);
    convert_store(0);
    __syncthreads();
    if (nch > 1) load_regs(1);

    for (int c = 0; c < nch; c++) {
        const int p = c & 1;
        if (c + 1 < nch) convert_store(p ^ 1);
        if (c + 2 < nch) load_regs(c + 2);

        const u32* Ah = pl + (p * 4 + 0) * PLANE_U32;
        const u32* Am = pl + (p * 4 + 1) * PLANE_U32;
        const u32* Bh = pl + (p * 4 + 2) * PLANE_U32;
        const u32* Bm = pl + (p * 4 + 3) * PLANE_U32;

#pragma unroll
        for (int ks = 0; ks < 2; ks++) {
            const int kc = ks * 8 + tig;
            u32 ah[4][4], am[4][4];
#pragma unroll
            for (int mi = 0; mi < 4; mi++) {
                const int r0 = (wm + mi * 16 + g) * LDH;
                const int r1 = r0 + 8 * LDH;
                ah[mi][0] = Ah[r0 + kc]; ah[mi][1] = Ah[r1 + kc];
                ah[mi][2] = Ah[r0 + kc + 4]; ah[mi][3] = Ah[r1 + kc + 4];
                am[mi][0] = Am[r0 + kc]; am[mi][1] = Am[r1 + kc];
                am[mi][2] = Am[r0 + kc + 4]; am[mi][3] = Am[r1 + kc + 4];
            }
#pragma unroll
            for (int ni = 0; ni < 4; ni++) {
                const int rn = (wn + ni * 8 + g) * LDH;
                const u32 bh0 = Bh[rn + kc], bh1 = Bh[rn + kc + 4];
                const u32 bm0 = Bm[rn + kc], bm1 = Bm[rn + kc + 4];
#pragma unroll
                for (int mi = 0; mi < 4; mi++) mma16(acc[mi][ni], ah[mi], bh0, bh1);
#pragma unroll
                for (int mi = 0; mi < 4; mi++) mma16(acc[mi][ni], am[mi], bh0, bh1);
#pragma unroll
                for (int mi = 0; mi < 4; mi++) mma16(acc[mi][ni], ah[mi], bm0, bm1);
            }
        }
        __syncthreads();
    }

    // epilogue: bias -> fp16 {h,m} planes (scaled by OPSCALE)
    __half* Chz = Ch + z * sC;
    __half* Cmz = Cm + z * sC;
#pragma unroll
    for (int mi = 0; mi < 4; mi++) {
        const int row0 = blockIdx.y * 128 + wm + mi * 16 + g;
        const float br0 = (bias && biasRow) ? bias[row0] : 0.0f;
        const float br1 = (bias && biasRow) ? bias[row0 + 8] : 0.0f;
#pragma unroll
        for (int ni = 0; ni < 4; ni++) {
            const int col0 = blockIdx.x * 128 + wn + ni * 8 + tig * 2;
            float v[4];
            v[0] = acc[mi][ni][0] * INVSC; v[1] = acc[mi][ni][1] * INVSC;
            v[2] = acc[mi][ni][2] * INVSC; v[3] = acc[mi][ni][3] * INVSC;
            if (bias) {
                if (biasRow) { v[0] += br0; v[1] += br0; v[2] += br1; v[3] += br1; }
                else {
                    const float b0 = bias[col0], b1 = bias[col0 + 1];
                    v[0] += b0; v[1] += b1; v[2] += b0; v[3] += b1;
                }
            }
            u32 h0, m0, h1, m1;
            split2(v[0] * OPSCALE, v[1] * OPSCALE, h0, m0);
            split2(v[2] * OPSCALE, v[3] * OPSCALE, h1, m1);
            const size_t o0 = (size_t)row0 * ldc + col0;
            const size_t o1 = (size_t)(row0 + 8) * ldc + col0;
            *(u32*)(Chz + o0) = h0; *(u32*)(Cmz + o0) = m0;
            *(u32*)(Chz + o1) = h1; *(u32*)(Cmz + o1) = m1;
        }
    }
}

// ---------------------------------------------------------------------------
// gemm_big: fp16 {h,m} plane operands (pre-scaled), fp32 out.
// CTA 128x128, KC=32, 256 thr, warp 64x32. cp.async plane fill (no convert,
// no register prefetch) -> 2 CTAs/SM. Two-pass MMA keeps regs < 128.
// nprod: 3 = hh+mh+hm (QK), 2 = hh+mh (PV: Bm never loaded).
// ---------------------------------------------------------------------------
__global__ __launch_bounds__(256, 2) void gemm_big(
    const __half* __restrict__ Ahg, const __half* __restrict__ Amg,
    const __half* __restrict__ Bhg, const __half* __restrict__ Bmg,
    float* __restrict__ C, int K, float scale,
    size_t sA, size_t sB, size_t sC, int ldc, int nprod)
{
    extern __shared__ u32 pl[];
    const u32 sbase = smem_u32(pl);
    const int tid = threadIdx.x;
    const int wid = tid >> 5, lane = tid & 31;
    const int g = lane >> 2, tig = lane & 3;
    const int wm = (wid >> 2) * 64, wn = (wid & 3) * 32;
    const int z = blockIdx.z;

    const __half* Ab[2] = { Ahg + z * sA + (size_t)(blockIdx.y * 128) * K,
                            Amg + z * sA + (size_t)(blockIdx.y * 128) * K };
    const __half* Bb[2] = { Bhg + z * sB + (size_t)(blockIdx.x * 128) * K,
                            Bmg + z * sB + (size_t)(blockIdx.x * 128) * K };

    float acc[4][4][4];
#pragma unroll
    for (int mi = 0; mi < 4; mi++)
#pragma unroll
        for (int ni = 0; ni < 4; ni++)
#pragma unroll
            for (int r = 0; r < 4; r++) acc[mi][ni][r] = 0.0f;

    const int nch = K / 32;
    const int nbp = (nprod == 3) ? 2 : 1;    // B planes loaded

    auto issue = [&](int c, int buf) {
        const int k0 = c * 32;
        const u32 s0 = sbase + (u32)(buf * 4 * PLANE_U32) * 4;
#pragma unroll
        for (int i = 0; i < 2; i++) {
            const int slot = tid + i * 256;          // 0..511
            const int row = slot >> 2;               // 0..127
            const int c4 = (slot & 3) * 4;           // u32 col
            const u32 soff = (u32)(row * LDH + c4) * 4;
            const size_t goff = (size_t)row * K + k0 + c4 * 2;
            cp16(s0 + 0 * PLANE_U32 * 4 + soff, Ab[0] + goff);
            cp16(s0 + 1 * PLANE_U32 * 4 + soff, Ab[1] + goff);
            cp16(s0 + 2 * PLANE_U32 * 4 + soff, Bb[0] + goff);
            if (nbp == 2) cp16(s0 + 3 * PLANE_U32 * 4 + soff, Bb[1] + goff);
        }
        CP_COMMIT();
    };

    issue(0, 0);

    for (int c = 0; c < nch; c++) {
        const int p = c & 1;
        CP_WAIT0();
        __syncthreads();
        if (c + 1 < nch) issue(c + 1, p ^ 1);

        const u32* Ah = pl + (p * 4 + 0) * PLANE_U32;
        const u32* Am = pl + (p * 4 + 1) * PLANE_U32;
        const u32* Bh = pl + (p * 4 + 2) * PLANE_U32;
        const u32* Bm = pl + (p * 4 + 3) * PLANE_U32;

#pragma unroll
        for (int ks = 0; ks < 2; ks++) {
            const int kc = ks * 8 + tig;
            // pass 1: ah-based products (hh, and hm if nprod==3)
            {
                u32 af[4][4];
#pragma unroll
                for (int mi = 0; mi < 4; mi++) {
                    const int r0 = (wm + mi * 16 + g) * LDH;
                    const int r1 = r0 + 8 * LDH;
                    af[mi][0] = Ah[r0 + kc]; af[mi][1] = Ah[r1 + kc];
                    af[mi][2] = Ah[r0 + kc + 4]; af[mi][3] = Ah[r1 + kc + 4];
                }
#pragma unroll
                for (int ni = 0; ni < 4; ni++) {
                    const int rn = (wn + ni * 8 + g) * LDH;
                    const u32 bh0 = Bh[rn + kc], bh1 = Bh[rn + kc + 4];
#pragma unroll
                    for (int mi = 0; mi < 4; mi++) mma16(acc[mi][ni], af[mi], bh0, bh1);
                    if (nprod == 3) {
                        const u32 bm0 = Bm[rn + kc], bm1 = Bm[rn + kc + 4];
#pragma unroll
                        for (int mi = 0; mi < 4; mi++) mma16(acc[mi][ni], af[mi], bm0, bm1);
                    }
                }
            }
            // pass 2: am-based product (mh)
            {
                u32 af[4][4];
#pragma unroll
                for (int mi = 0; mi < 4; mi++) {
                    const int r0 = (wm + mi * 16 + g) * LDH;
                    const int r1 = r0 + 8 * LDH;
                    af[mi][0] = Am[r0 + kc]; af[mi][1] = Am[r1 + kc];
                    af[mi][2] = Am[r0 + kc + 4]; af[mi][3] = Am[r1 + kc + 4];
                }
#pragma unroll
                for (int ni = 0; ni < 4; ni++) {
                    const int rn = (wn + ni * 8 + g) * LDH;
                    const u32 bh0 = Bh[rn + kc], bh1 = Bh[rn + kc + 4];
#pragma unroll
                    for (int mi = 0; mi < 4; mi++) mma16(acc[mi][ni], af[mi], bh0, bh1);
                }
            }
        }
        __syncthreads();
    }

    // epilogue
    float* Cz = C + z * sC;
#pragma unroll
    for (int mi = 0; mi < 4; mi++) {
        const int row0 = blockIdx.y * 128 + wm + mi * 16 + g;
#pragma unroll
        for (int ni = 0; ni < 4; ni++) {
            const int col0 = blockIdx.x * 128 + wn + ni * 8 + tig * 2;
            float2 v0, v1;
            v0.x = acc[mi][ni][0] * scale; v0.y = acc[mi][ni][1] * scale;
            v1.x = acc[mi][ni][2] * scale; v1.y = acc[mi][ni][3] * scale;
            *(float2*)(Cz + (size_t)row0 * ldc + col0) = v0;
            *(float2*)(Cz + (size_t)(row0 + 8) * ldc + col0) = v1;
        }
    }
}

// ---------------------------------------------------------------------------
// In-place row softmax + fp16 {h,m} plane output (scaled by OPSCALE).
// ---------------------------------------------------------------------------
__global__ __launch_bounds__(256) void softmax_k(float* __restrict__ P,
    __half* __restrict__ ph, __half* __restrict__ pm)
{
    const size_t base = (size_t)blockIdx.x * SEQ;
    float* p = P + base;
    const int tid = threadIdx.x, lane = tid & 31, wid = tid >> 5;
    float4 a = ((const float4*)p)[tid * 2 + 0];
    float4 b = ((const float4*)p)[tid * 2 + 1];
    float x[8] = {a.x, a.y, a.z, a.w, b.x, b.y, b.z, b.w};
    __shared__ float red[8];

    float m = -INFINITY;
#pragma unroll
    for (int i = 0; i < 8; i++) m = fmaxf(m, x[i]);
#pragma unroll
    for (int o = 16; o > 0; o >>= 1) m = fmaxf(m, __shfl_xor_sync(0xffffffffu, m, o));
    if (lane == 0) red[wid] = m;
    __syncthreads();
    float mr = -INFINITY;
#pragma unroll
    for (int i = 0; i < 8; i++) mr = fmaxf(mr, red[i]);
    __syncthreads();

    float s = 0.0f;
#pragma unroll
    for (int i = 0; i < 8; i++) { x[i] = expf(x[i] - mr); s += x[i]; }
#pragma unroll
    for (int o = 16; o > 0; o >>= 1) s += __shfl_xor_sync(0xffffffffu, s, o);
    if (lane == 0) red[wid] = s;
    __syncthreads();
    float tot = 0.0f;
#pragma unroll
    for (int i = 0; i < 8; i++) tot += red[i];
    const float inv = 1.0f / tot;

    float4 o0, o1;
    o0.x = x[0] * inv; o0.y = x[1] * inv; o0.z = x[2] * inv; o0.w = x[3] * inv;
    o1.x = x[4] * inv; o1.y = x[5] * inv; o1.z = x[6] * inv; o1.w = x[7] * inv;
    ((float4*)p)[tid * 2 + 0] = o0;
    ((float4*)p)[tid * 2 + 1] = o1;

    float y[8] = {o0.x, o0.y, o0.z, o0.w, o1.x, o1.y, o1.z, o1.w};
#pragma unroll
    for (int i = 0; i < 8; i += 2) {
        u32 hp, mp;
        split2(y[i] * OPSCALE, y[i + 1] * OPSCALE, hp, mp);
        const size_t off = base + tid * 8 + i;
        *(u32*)(ph + off) = hp;
        *(u32*)(pm + off) = mp;
    }
}

// ---------------------------------------------------------------------------
extern "C" void kernel_launch(void* const* d_in, const int* in_sizes, int n_in,
                              void* d_out, int out_size)
{
    const float* query = (const float*)d_in[0];
    const float* key   = (const float*)d_in[1];
    const float* value = (const float*)d_in[2];
    const float* Wq = (const float*)d_in[3]; const float* bq = (const float*)d_in[4];
    const float* Wk = (const float*)d_in[5]; const float* bk = (const float*)d_in[6];
    const float* Wv = (const float*)d_in[7]; const float* bv = (const float*)d_in[8];

    float* out_attn = (float*)d_out;
    float* out_smax = (float*)d_out + (size_t)MSZ * DIM;

    __half *qh, *qm, *kh, *km, *vth, *vtm, *ph, *pm;
    cudaGetSymbolAddress((void**)&qh,  g_qh);  cudaGetSymbolAddress((void**)&qm,  g_qm);
    cudaGetSymbolAddress((void**)&kh,  g_kh);  cudaGetSymbolAddress((void**)&km,  g_km);
    cudaGetSymbolAddress((void**)&vth, g_vth); cudaGetSymbolAddress((void**)&vtm, g_vtm);
    cudaGetSymbolAddress((void**)&ph,  g_ph);  cudaGetSymbolAddress((void**)&pm,  g_pm);

    cudaFuncSetAttribute(gemm_proj, cudaFuncAttributeMaxDynamicSharedMemorySize, SMEM_BYTES);
    cudaFuncSetAttribute(gemm_big,  cudaFuncAttributeMaxDynamicSharedMemorySize, SMEM_BYTES);

    // 1) q/k projections -> fp16 planes
    {
        dim3 grid(DIM / 128, MSZ / 128, 1);
        gemm_proj<<<grid, 256, SMEM_BYTES>>>(query, Wq, bq, 0, qh, qm, DIM, 0, 0, 0, DIM);
        gemm_proj<<<grid, 256, SMEM_BYTES>>>(key,   Wk, bk, 0, kh, km, DIM, 0, 0, 0, DIM);
    }
    // 2) vT[b,e,s] = Wv[e,:] . value[b,s,:] + bv[e] -> planes
    {
        dim3 grid(SEQ / 128, DIM / 128, BATCH);
        gemm_proj<<<grid, 256, SMEM_BYTES>>>(Wv, value, bv, 1, vth, vtm, DIM,
                                             0, (size_t)SEQ * DIM, (size_t)DIM * SEQ, SEQ);
    }
    // 3) scores = 10 * q @ k^T   (3 products)
    {
        dim3 grid(SEQ / 128, SEQ / 128, BATCH);
        gemm_big<<<grid, 256, SMEM_BYTES>>>(qh, qm, kh, km, out_smax, DIM, 10.0f * INVSC,
                                            (size_t)SEQ * DIM, (size_t)SEQ * DIM,
                                            (size_t)SEQ * SEQ, SEQ, 3);
    }
    // 4) softmax in place + P planes
    softmax_k<<<MSZ, 256>>>(out_smax, ph, pm);
    // 5) out = P @ vT^T   (2 products: hh + mh; v-mid plane never loaded)
    {
        dim3 grid(DIM / 128, SEQ / 128, BATCH);
        gemm_big<<<grid, 256, SMEM_BYTES>>>(ph, pm, vth, vtm, out_attn, SEQ, INVSC,
                                            (size_t)SEQ * SEQ, (size_t)DIM * SEQ,
                                            (size_t)SEQ * DIM, DIM, 2);
    }
}